// round 1
// baseline (speedup 1.0000x reference)
#include <cuda_runtime.h>
#include <math.h>

#define BB 8
#define CC 12
#define NN 785
#define SS 784
#define HH 28
#define DD 768
#define PATCH 84
#define NT 256

// Scratch (allocation-free: __device__ globals)
__device__ float  g_newscore[BB * CC * SS];
__device__ int    g_count0[BB * SS];
__device__ float4 g_addvec4[BB * DD / 4];
__device__ int    g_patchidx[BB * 64];

// ---------------------------------------------------------------------------
// Bitonic descending sort of 1024 keys in shared memory, 256 threads.
// ---------------------------------------------------------------------------
template <typename T>
__device__ inline void bitonic_desc_1024(T* key, int tid) {
    for (int k = 2; k <= 1024; k <<= 1) {
        for (int j = k >> 1; j > 0; j >>= 1) {
            __syncthreads();
            #pragma unroll
            for (int t = 0; t < 4; t++) {
                int i = tid + t * 256;
                int ix = i ^ j;
                if (ix > i) {
                    T a = key[i], b = key[ix];
                    bool down = ((i & k) == 0);
                    if (down ? (a < b) : (a > b)) { key[i] = b; key[ix] = a; }
                }
            }
        }
    }
    __syncthreads();
}

// ---------------------------------------------------------------------------
// Kernel 0: zero the scatter-count buffer (persists across graph replays).
// ---------------------------------------------------------------------------
__global__ void init_kernel() {
    int i = blockIdx.x * blockDim.x + threadIdx.x;
    if (i < BB * SS) g_count0[i] = 0;
}

// ---------------------------------------------------------------------------
// Kernel A: per (b, c): top-84 of score = x[b,c,0,1:], write
// new_score = select ? score : 0.7*score, accumulate count0.
// ---------------------------------------------------------------------------
__global__ void __launch_bounds__(NT) topk_kernel(const float* __restrict__ x) {
    int b = blockIdx.x / CC;
    int c = blockIdx.x % CC;
    int tid = threadIdx.x;

    __shared__ float sc[SS];
    __shared__ unsigned char selm[SS];
    __shared__ unsigned long long key[1024];

    const float* row = x + ((size_t)(b * CC + c) * NN) * NN + 1;  // x[b,c,0,1:]
    for (int s = tid; s < SS; s += NT) {
        float v = row[s];
        sc[s] = v;
        selm[s] = 0;
        unsigned u = __float_as_uint(v);
        unsigned ord = (u & 0x80000000u) ? ~u : (u | 0x80000000u);  // order-preserving
        key[s] = ((unsigned long long)ord << 10) | (unsigned)(1023 - s);
    }
    for (int s = SS + tid; s < 1024; s += NT) key[s] = 0ULL;

    bitonic_desc_1024(key, tid);

    if (tid < PATCH) {
        int s = 1023 - (int)(key[tid] & 1023ULL);
        selm[s] = 1;
        atomicAdd(&g_count0[b * SS + s], 1);
    }
    __syncthreads();

    float* ns = g_newscore + (b * CC + c) * SS;
    for (int s = tid; s < SS; s += NT)
        ns[s] = selm[s] ? sc[s] : sc[s] * 0.7f;
}

// ---------------------------------------------------------------------------
// Kernel B: per batch b — pw, binary/mean, anchor argmax, structure sums,
// collapsed rank-1 GCN, 3x3 count conv, stable descending sort -> patch_idx.
// ---------------------------------------------------------------------------
__global__ void __launch_bounds__(NT) gcn_kernel(const float* __restrict__ w1,
                                                 const float* __restrict__ w2,
                                                 int SEL) {
    int b = blockIdx.x;
    int tid = threadIdx.x;

    __shared__ float pw[SS];
    __shared__ int   cc[SS];
    __shared__ float u[512];
    __shared__ int   keys[1024];
    __shared__ double dred[NT];
    __shared__ float  fred[NT];
    __shared__ int    ired[NT];
    __shared__ float4 red4[NT];
    __shared__ float s_mean, s_pwa, s_sv0, s_sv1, s_Pp, s_Pn;
    __shared__ int s_anchor;

    // --- pw[s] = mean_c new_score ; load counts ; sum for mean ---
    double dsum = 0.0;
    for (int s = tid; s < SS; s += NT) {
        const float* nsb = g_newscore + b * CC * SS + s;
        float m = 0.f;
        #pragma unroll
        for (int c = 0; c < CC; c++) m += nsb[c * SS];
        float p = m / 12.0f;
        pw[s] = p;
        cc[s] = g_count0[b * SS + s];
        dsum += (double)p;
    }
    dred[tid] = dsum;
    __syncthreads();
    for (int off = NT / 2; off > 0; off >>= 1) {
        if (tid < off) dred[tid] += dred[tid + off];
        __syncthreads();
    }
    if (tid == 0) s_mean = (float)(dred[0] / 784.0);
    __syncthreads();
    float mean = s_mean;

    // --- anchor = argmax_s (pw[s] > mean ? pw[s] : 0), first occurrence ---
    float bestv = -3.0e38f;
    int besti = 1 << 30;
    for (int s = tid; s < SS; s += NT) {
        float v = (pw[s] > mean) ? pw[s] : 0.0f;
        if (v > bestv || (v == bestv && s < besti)) { bestv = v; besti = s; }
    }
    fred[tid] = bestv; ired[tid] = besti;
    __syncthreads();
    for (int off = NT / 2; off > 0; off >>= 1) {
        if (tid < off) {
            float v2 = fred[tid + off]; int i2 = ired[tid + off];
            if (v2 > fred[tid] || (v2 == fred[tid] && i2 < ired[tid])) {
                fred[tid] = v2; ired[tid] = i2;
            }
        }
        __syncthreads();
    }
    if (tid == 0) { s_anchor = ired[0]; s_pwa = pw[ired[0]]; }
    __syncthreads();
    int anchor = s_anchor;
    int ai = anchor / HH, aj = anchor % HH;

    // --- sv = sum_s pw[s]*(dist,ang); Pp/Pn = sum pw^2 over sign classes ---
    float sv0 = 0.f, sv1 = 0.f, Pp = 0.f, Pn = 0.f;
    const float PI_F = 3.14159265358979323846f;
    for (int s = tid; s < SS; s += NT) {
        int i = s / HH, j = s - i * HH;
        float rx = (float)(i - ai) / 28.0f;
        float ry = (float)(j - aj) / 28.0f;
        float dist = sqrtf(rx * rx + ry * ry);
        float ang = (atan2f(ry, rx) / PI_F + 1.0f) / 2.0f;
        float p = pw[s];
        sv0 += p * dist;
        sv1 += p * ang;
        if (p > 0.f) Pp += p * p;
        else if (p < 0.f) Pn += p * p;
    }
    red4[tid] = make_float4(sv0, sv1, Pp, Pn);
    __syncthreads();
    for (int off = NT / 2; off > 0; off >>= 1) {
        if (tid < off) {
            float4 a = red4[tid], bb = red4[tid + off];
            red4[tid] = make_float4(a.x + bb.x, a.y + bb.y, a.z + bb.z, a.w + bb.w);
        }
        __syncthreads();
    }
    if (tid == 0) {
        s_sv0 = red4[0].x; s_sv1 = red4[0].y; s_Pp = red4[0].z; s_Pn = red4[0].w;
    }
    __syncthreads();
    float vsv0 = s_sv0, vsv1 = s_sv1, vPp = s_Pp, vPn = s_Pn;

    // --- u[j] = v1[j] * (v1>0 ? Pp : Pn), v1 = sv @ w1 ---
    for (int j = tid; j < 512; j += NT) {
        float v1 = vsv0 * w1[j] + vsv1 * w1[512 + j];
        u[j] = v1 * (v1 > 0.f ? vPp : vPn);
    }
    __syncthreads();

    // --- addvec[k] = leakyrelu(pw[anchor] * (u @ w2)[k]) ---
    float pwa = s_pwa;
    for (int k = tid; k < DD; k += NT) {
        float acc = 0.f;
        #pragma unroll 8
        for (int j = 0; j < 512; j++) acc += u[j] * w2[j * DD + k];
        float o = pwa * acc;
        ((float*)g_addvec4)[b * DD + k] = (o > 0.f) ? o : 0.2f * o;
    }

    // --- 3x3 [1,2,1;2,4,2;1,2,1] SAME conv on counts, build sortable keys ---
    for (int s = tid; s < SS; s += NT) {
        int i = s / HH, j = s - i * HH;
        int acc = 0;
        #pragma unroll
        for (int di = -1; di <= 1; di++) {
            int ii = i + di;
            if (ii < 0 || ii >= HH) continue;
            #pragma unroll
            for (int dj = -1; dj <= 1; dj++) {
                int jj = j + dj;
                if (jj < 0 || jj >= HH) continue;
                int wgt = (2 - (di < 0 ? -di : di)) * (2 - (dj < 0 ? -dj : dj));
                acc += wgt * cc[ii * HH + jj];
            }
        }
        keys[s] = (acc << 10) | (1023 - s);  // desc count, tie -> asc index
    }
    for (int s = SS + tid; s < 1024; s += NT) keys[s] = 0;

    bitonic_desc_1024(keys, tid);

    if (tid < SEL)
        g_patchidx[b * 64 + tid] = (1023 - (keys[tid] & 1023)) + 1;
}

// ---------------------------------------------------------------------------
// Kernel C: write out = [hs (B,N,D) with row0 += addvec ; selected (B,SEL,D)]
// float4-vectorized.
// ---------------------------------------------------------------------------
__global__ void __launch_bounds__(NT) out_kernel(const float4* __restrict__ hid4,
                                                 float4* __restrict__ out4,
                                                 int SEL, int total4) {
    int idx = blockIdx.x * blockDim.x + threadIdx.x;
    if (idx >= total4) return;
    const int D4 = DD / 4;         // 192
    const int ND4 = NN * D4;       // 150720
    const int HS4 = BB * ND4;

    if (idx < HS4) {
        int b = idx / ND4;
        int r = idx - b * ND4;
        float4 v = hid4[idx];
        if (r < D4) {
            float4 a = g_addvec4[b * D4 + r];
            v.x += a.x; v.y += a.y; v.z += a.z; v.w += a.w;
        }
        out4[idx] = v;
    } else {
        int q = idx - HS4;
        int per_b = SEL * D4;
        int b = q / per_b;
        int r = q - b * per_b;
        int i = r / D4;
        int k4 = r - i * D4;
        int row = g_patchidx[b * 64 + i];
        out4[idx] = hid4[(b * NN + row) * D4 + k4];
    }
}

// ---------------------------------------------------------------------------
extern "C" void kernel_launch(void* const* d_in, const int* in_sizes, int n_in,
                              void* d_out, int out_size) {
    const float* hidden = (const float*)d_in[0];
    const float* x      = (const float*)d_in[1];
    const float* w1     = (const float*)d_in[2];
    const float* w2     = (const float*)d_in[3];
    // select_num recovered from out_size (output = concat[hs, selected])
    int SEL = (out_size - BB * NN * DD) / (BB * DD);

    init_kernel<<<(BB * SS + NT - 1) / NT, NT>>>();
    topk_kernel<<<BB * CC, NT>>>(x);
    gcn_kernel<<<BB, NT>>>(w1, w2, SEL);
    int total4 = out_size / 4;
    out_kernel<<<(total4 + NT - 1) / NT, NT>>>((const float4*)hidden,
                                               (float4*)d_out, SEL, total4);
}

// round 3
// speedup vs baseline: 2.5375x; 2.5375x over previous
#include <cuda_runtime.h>
#include <math.h>

#define BB 8
#define CC 12
#define NN 785
#define SS 784
#define HH 28
#define DD 768
#define PATCH 84

// Scratch (allocation-free: __device__ globals)
__device__ float         g_newscore[BB * CC * SS];
__device__ unsigned char g_sel[BB * CC * SS];
__device__ float         g_u[BB * 512];
__device__ float         g_pwa[BB];
__device__ int           g_patchidx[BB * 64];

// ---------------------------------------------------------------------------
// Exact k-th-largest selection over vals[0..n) via MSB-first byte radix.
// Requires blockDim.x == 256. Returns T (k-th largest value) and
// rem = k - count(vals > T)  (number of ties at T to take, smallest-index-first).
// ---------------------------------------------------------------------------
__device__ __forceinline__ void radix_select_desc(const unsigned* __restrict__ vals,
                                                  int n, int k,
                                                  unsigned* T_out, int* rem_out) {
    __shared__ unsigned rs_hist[256];
    __shared__ unsigned rs_wsum[8];
    __shared__ unsigned rs_pref;
    __shared__ int      rs_kk;
    int tid = threadIdx.x;
    unsigned prefix = 0, pmask = 0;
    int kk = k;
    #pragma unroll
    for (int pass = 0; pass < 4; pass++) {
        int shift = 24 - 8 * pass;
        rs_hist[tid] = 0;
        __syncthreads();
        for (int i = tid; i < n; i += 256) {
            unsigned v = vals[i];
            if ((v & pmask) == prefix)
                atomicAdd(&rs_hist[(v >> shift) & 255u], 1u);
        }
        __syncthreads();
        // suffix sums over bins: tid maps to bin 255-tid (descending bins)
        int w = tid >> 5, l = tid & 31;
        unsigned own = rs_hist[255 - tid];
        unsigned v = own;
        #pragma unroll
        for (int o = 1; o < 32; o <<= 1) {
            unsigned up = __shfl_up_sync(0xffffffffu, v, o);
            if (l >= o) v += up;
        }
        if (l == 31) rs_wsum[w] = v;
        __syncthreads();
        unsigned add = 0;
        #pragma unroll
        for (int ww = 0; ww < 8; ww++) add += (ww < w) ? rs_wsum[ww] : 0u;
        unsigned incl = v + add;        // count(candidates with byte >= this bin)
        unsigned excl = incl - own;     // count(candidates with byte >  this bin)
        if ((int)incl >= kk && (int)excl < kk) {
            rs_pref = prefix | ((unsigned)(255 - tid) << shift);
            rs_kk = kk - (int)excl;
        }
        __syncthreads();
        prefix = rs_pref;
        kk = rs_kk;
        pmask |= (0xFFu << shift);
        __syncthreads();
    }
    *T_out = prefix;
    *rem_out = kk;
}

// ---------------------------------------------------------------------------
// Kernel A: per (b, c): exact top-84 of score = x[b,c,0,1:]; write
// new_score = select ? score : 0.7*score and the select mask byte.
// ---------------------------------------------------------------------------
__global__ void __launch_bounds__(256) topk_kernel(const float* __restrict__ x) {
    int b = blockIdx.x / CC;
    int c = blockIdx.x % CC;
    int tid = threadIdx.x;

    __shared__ unsigned ord[SS];
    __shared__ float sc[SS];
    __shared__ unsigned char selm[SS];
    __shared__ int tk_w[8];

    const float* row = x + ((size_t)(b * CC + c) * NN) * NN + 1;  // x[b,c,0,1:]
    for (int s = tid; s < SS; s += 256) {
        float v = row[s];
        sc[s] = v;
        unsigned u = __float_as_uint(v);
        ord[s] = (u & 0x80000000u) ? ~u : (u | 0x80000000u);  // order-preserving
    }
    __syncthreads();

    unsigned T; int rem;
    radix_select_desc(ord, SS, PATCH, &T, &rem);

    // Tie scan: thread t owns contiguous s in [4t, 4t+4)  (784 = 4*196)
    int cnt = 0;
    if (tid < 196) {
        #pragma unroll
        for (int e = 0; e < 4; e++) cnt += (ord[4 * tid + e] == T);
    }
    // exclusive block scan of cnt
    int w = tid >> 5, l = tid & 31;
    int v = cnt;
    #pragma unroll
    for (int o = 1; o < 32; o <<= 1) {
        int up = __shfl_up_sync(0xffffffffu, v, o);
        if (l >= o) v += up;
    }
    if (l == 31) tk_w[w] = v;
    __syncthreads();
    int add = 0;
    #pragma unroll
    for (int ww = 0; ww < 8; ww++) add += (ww < w) ? tk_w[ww] : 0;
    int base = v - cnt + add;  // #ties with index < 4*tid

    if (tid < 196) {
        int run = base;
        #pragma unroll
        for (int e = 0; e < 4; e++) {
            int s = 4 * tid + e;
            unsigned o = ord[s];
            bool sel;
            if (o > T) sel = true;
            else if (o == T) { sel = (run < rem); run++; }
            else sel = false;
            selm[s] = sel ? 1 : 0;
        }
    }
    __syncthreads();

    float* ns = g_newscore + (b * CC + c) * SS;
    unsigned char* gs = g_sel + (b * CC + c) * SS;
    for (int s = tid; s < SS; s += 256) {
        unsigned char m = selm[s];
        ns[s] = m ? sc[s] : sc[s] * 0.7f;
        gs[s] = m;
    }
}

// ---------------------------------------------------------------------------
// Kernel B: per batch b — pw, mean/binary, anchor argmax, structure sums,
// rank-1-collapsed GCN scalars (u vector), 3x3 count conv + ordered top-SEL.
// ---------------------------------------------------------------------------
__global__ void __launch_bounds__(256) gcn_kernel(const float* __restrict__ w1,
                                                  int SEL) {
    int b = blockIdx.x;
    int tid = threadIdx.x;

    __shared__ float pw[SS];
    __shared__ int   cc[SS];
    __shared__ unsigned keys[SS];
    __shared__ double dred[256];
    __shared__ float  fred[256];
    __shared__ int    ired[256];
    __shared__ float4 red4[256];
    __shared__ float s_mean, s_sv0, s_sv1, s_Pp, s_Pn;
    __shared__ int s_anchor;
    __shared__ unsigned sel_list[64];
    __shared__ int sel_cnt;

    // --- pw[s] = mean_c new_score; counts; sum for mean ---
    double dsum = 0.0;
    for (int s = tid; s < SS; s += 256) {
        const float* nsb = g_newscore + b * CC * SS + s;
        const unsigned char* gsb = g_sel + b * CC * SS + s;
        float m = 0.f;
        int ct = 0;
        #pragma unroll
        for (int c = 0; c < CC; c++) { m += nsb[c * SS]; ct += gsb[c * SS]; }
        float p = m / 12.0f;
        pw[s] = p;
        cc[s] = ct;
        dsum += (double)p;
    }
    dred[tid] = dsum;
    __syncthreads();
    for (int off = 128; off > 0; off >>= 1) {
        if (tid < off) dred[tid] += dred[tid + off];
        __syncthreads();
    }
    if (tid == 0) s_mean = (float)(dred[0] / 784.0);
    __syncthreads();
    float mean = s_mean;

    // --- anchor = argmax_s (pw[s] > mean ? pw[s] : 0), first occurrence ---
    float bestv = -3.0e38f;
    int besti = 1 << 30;
    for (int s = tid; s < SS; s += 256) {
        float vv = (pw[s] > mean) ? pw[s] : 0.0f;
        if (vv > bestv || (vv == bestv && s < besti)) { bestv = vv; besti = s; }
    }
    fred[tid] = bestv; ired[tid] = besti;
    __syncthreads();
    for (int off = 128; off > 0; off >>= 1) {
        if (tid < off) {
            float v2 = fred[tid + off]; int i2 = ired[tid + off];
            if (v2 > fred[tid] || (v2 == fred[tid] && i2 < ired[tid])) {
                fred[tid] = v2; ired[tid] = i2;
            }
        }
        __syncthreads();
    }
    if (tid == 0) {
        s_anchor = ired[0];
        g_pwa[b] = pw[ired[0]];
    }
    __syncthreads();
    int anchor = s_anchor;
    int ai = anchor / HH, aj = anchor % HH;

    // --- sv = sum_s pw[s]*(dist,ang); Pp/Pn = sum pw^2 by sign ---
    float sv0 = 0.f, sv1 = 0.f, Pp = 0.f, Pn = 0.f;
    const float PI_F = 3.14159265358979323846f;
    for (int s = tid; s < SS; s += 256) {
        int i = s / HH, j = s - i * HH;
        float rx = (float)(i - ai) / 28.0f;
        float ry = (float)(j - aj) / 28.0f;
        float dist = sqrtf(rx * rx + ry * ry);
        float ang = (atan2f(ry, rx) / PI_F + 1.0f) / 2.0f;
        float p = pw[s];
        sv0 += p * dist;
        sv1 += p * ang;
        if (p > 0.f) Pp += p * p;
        else if (p < 0.f) Pn += p * p;
    }
    red4[tid] = make_float4(sv0, sv1, Pp, Pn);
    __syncthreads();
    for (int off = 128; off > 0; off >>= 1) {
        if (tid < off) {
            float4 a = red4[tid], b2 = red4[tid + off];
            red4[tid] = make_float4(a.x + b2.x, a.y + b2.y, a.z + b2.z, a.w + b2.w);
        }
        __syncthreads();
    }
    if (tid == 0) {
        s_sv0 = red4[0].x; s_sv1 = red4[0].y; s_Pp = red4[0].z; s_Pn = red4[0].w;
    }
    __syncthreads();
    float vsv0 = s_sv0, vsv1 = s_sv1, vPp = s_Pp, vPn = s_Pn;

    // --- u[j] = v1[j] * (v1>0 ? Pp : Pn), v1 = sv @ w1 ---
    for (int j = tid; j < 512; j += 256) {
        float v1 = vsv0 * w1[j] + vsv1 * w1[512 + j];
        g_u[b * 512 + j] = v1 * (v1 > 0.f ? vPp : vPn);
    }

    // --- 3x3 [1,2,1;2,4,2;1,2,1] SAME conv on counts -> sortable keys ---
    for (int s = tid; s < SS; s += 256) {
        int i = s / HH, j = s - i * HH;
        int acc = 0;
        #pragma unroll
        for (int di = -1; di <= 1; di++) {
            int ii = i + di;
            if (ii < 0 || ii >= HH) continue;
            #pragma unroll
            for (int dj = -1; dj <= 1; dj++) {
                int jj = j + dj;
                if (jj < 0 || jj >= HH) continue;
                int wgt = (2 - (di < 0 ? -di : di)) * (2 - (dj < 0 ? -dj : dj));
                acc += wgt * cc[ii * HH + jj];
            }
        }
        keys[s] = ((unsigned)acc << 10) | (unsigned)(1023 - s);  // desc count, tie asc s
    }
    if (tid == 0) sel_cnt = 0;
    __syncthreads();

    unsigned T; int rem;
    radix_select_desc(keys, SS, SEL, &T, &rem);  // keys unique -> exactly SEL with key >= T

    for (int s = tid; s < SS; s += 256) {
        if (keys[s] >= T) {
            int p = atomicAdd(&sel_cnt, 1);
            sel_list[p] = keys[s];
        }
    }
    __syncthreads();
    if (tid < SEL) {
        unsigned mk = sel_list[tid];
        int r = 0;
        for (int m = 0; m < SEL; m++) r += (sel_list[m] > mk) ? 1 : 0;
        g_patchidx[b * 64 + r] = 1024 - (int)(mk & 1023u);  // (1023-(key&1023)) + 1
    }
}

// ---------------------------------------------------------------------------
// Kernel C: blocks 0..47 compute the w2 matvec + leaky-relu and write out
// row 0 (= hidden row 0 + addvec) for (b, 128-col chunk). Remaining blocks
// stream-copy hs rows 1..784 and the gathered selected rows, 2 float4/thread.
// ---------------------------------------------------------------------------
#define MV_BLOCKS 48

__global__ void __launch_bounds__(256) out_kernel(const float4* __restrict__ hid4,
                                                  float4* __restrict__ out4,
                                                  const float* __restrict__ w2,
                                                  int SEL, int copyA, int copyTot,
                                                  int G) {
    int blk = blockIdx.x;
    const int D4 = DD / 4;        // 192
    const int ND4 = NN * D4;      // 150720
    const int HS4 = BB * ND4;

    if (blk < MV_BLOCKS) {
        __shared__ float su[512];
        int b = blk / 6, kc = blk - b * 6;
        for (int i = threadIdx.x; i < 512; i += 256) su[i] = g_u[b * 512 + i];
        __syncthreads();
        if (threadIdx.x < 128) {
            int k = kc * 128 + threadIdx.x;
            const float* w2c = w2 + k;
            float a0 = 0.f, a1 = 0.f, a2 = 0.f, a3 = 0.f;
            #pragma unroll 4
            for (int j = 0; j < 512; j += 4) {
                a0 += su[j]     * w2c[(j)     * DD];
                a1 += su[j + 1] * w2c[(j + 1) * DD];
                a2 += su[j + 2] * w2c[(j + 2) * DD];
                a3 += su[j + 3] * w2c[(j + 3) * DD];
            }
            float o = g_pwa[b] * ((a0 + a1) + (a2 + a3));
            float res = (o > 0.f) ? o : 0.2f * o;
            size_t idx = (size_t)b * (NN * DD) + k;
            ((float*)out4)[idx] = ((const float*)hid4)[idx] + res;
        }
        return;
    }

    int q = (blk - MV_BLOCKS) * 256 + threadIdx.x;
    const int RPB = ND4 - D4;     // float4s per batch in rows 1..784
    #pragma unroll
    for (int rep = 0; rep < 2; rep++) {
        int qq = q + rep * G;
        if (qq < copyTot) {
            if (qq < copyA) {
                int b = qq / RPB;
                int r = qq - b * RPB;
                int idx = b * ND4 + D4 + r;
                out4[idx] = hid4[idx];
            } else {
                int q2 = qq - copyA;
                int perb = SEL * D4;
                int b = q2 / perb;
                int r = q2 - b * perb;
                int i = r / D4;
                int k4 = r - i * D4;
                int row = g_patchidx[b * 64 + i];
                out4[HS4 + q2] = hid4[(b * NN + row) * D4 + k4];
            }
        }
    }
}

// ---------------------------------------------------------------------------
extern "C" void kernel_launch(void* const* d_in, const int* in_sizes, int n_in,
                              void* d_out, int out_size) {
    const float* hidden = (const float*)d_in[0];
    const float* x      = (const float*)d_in[1];
    const float* w1     = (const float*)d_in[2];
    const float* w2     = (const float*)d_in[3];
    int SEL = (out_size - BB * NN * DD) / (BB * DD);

    topk_kernel<<<BB * CC, 256>>>(x);
    gcn_kernel<<<BB, 256>>>(w1, SEL);

    const int D4 = DD / 4, ND4 = NN * D4;
    int copyA   = BB * (ND4 - D4);
    int copyTot = copyA + BB * SEL * D4;
    int half    = (copyTot + 1) / 2;
    int NC      = (half + 255) / 256;
    int G       = NC * 256;
    out_kernel<<<MV_BLOCKS + NC, 256>>>((const float4*)hidden, (float4*)d_out,
                                        w2, SEL, copyA, copyTot, G);
}

// round 15
// speedup vs baseline: 3.3321x; 1.3131x over previous
#include <cuda_runtime.h>
#include <math.h>

#define BB 8
#define CC 12
#define NN 785
#define SS 784
#define HH 28
#define DD 768
#define PATCH 84
#define NTOPK (BB * CC)

// Scratch (allocation-free: __device__ globals; zero-initialized at load)
__device__ float         g_newscore[BB * CC * SS];
__device__ unsigned char g_sel[BB * CC * SS];
__device__ float         g_u[BB * 512];
__device__ float         g_pwa[BB];
__device__ int           g_patchidx[BB * 64];
__device__ unsigned      g_done[BB];   // monotonic across graph replays

// ---------------------------------------------------------------------------
// Exact k-th-largest over vals[0..n) via MSB-first byte radix, with early exit
// when the boundary bin holds a single candidate. blockDim.x == 256.
// Returns T (k-th largest) and rem = k - count(vals > T).
// ---------------------------------------------------------------------------
__device__ __forceinline__ void radix_select_desc(const unsigned* __restrict__ vals,
                                                  int n, int k,
                                                  unsigned* T_out, int* rem_out) {
    __shared__ unsigned rs_hist[256];
    __shared__ unsigned rs_wsum[8];
    __shared__ unsigned rs_pref;
    __shared__ int      rs_kk;
    __shared__ unsigned rs_own;
    __shared__ unsigned rs_T;
    int tid = threadIdx.x;
    unsigned prefix = 0, pmask = 0;
    int kk = k;
    for (int pass = 0; pass < 4; pass++) {
        int shift = 24 - 8 * pass;
        rs_hist[tid] = 0;
        __syncthreads();
        for (int i = tid; i < n; i += 256) {
            unsigned v = vals[i];
            if ((v & pmask) == prefix)
                atomicAdd(&rs_hist[(v >> shift) & 255u], 1u);
        }
        __syncthreads();
        int w = tid >> 5, l = tid & 31;
        unsigned own = rs_hist[255 - tid];   // descending bins
        unsigned v = own;
        #pragma unroll
        for (int o = 1; o < 32; o <<= 1) {
            unsigned up = __shfl_up_sync(0xffffffffu, v, o);
            if (l >= o) v += up;
        }
        if (l == 31) rs_wsum[w] = v;
        __syncthreads();
        unsigned add = 0;
        #pragma unroll
        for (int ww = 0; ww < 8; ww++) add += (ww < w) ? rs_wsum[ww] : 0u;
        unsigned incl = v + add;
        unsigned excl = incl - own;
        if ((int)incl >= kk && (int)excl < kk) {
            rs_pref = prefix | ((unsigned)(255 - tid) << shift);
            rs_kk   = kk - (int)excl;
            rs_own  = own;
        }
        __syncthreads();
        prefix = rs_pref;
        kk = rs_kk;
        pmask |= (0xFFu << shift);
        if (rs_own == 1u && pass < 3) {
            // unique candidate with this prefix IS the threshold value
            for (int i = tid; i < n; i += 256) {
                unsigned vv = vals[i];
                if ((vv & pmask) == prefix) rs_T = vv;
            }
            __syncthreads();
            prefix = rs_T;
            break;
        }
        if (rs_own == 1u) break;  // pass 3: prefix already the full value
    }
    *T_out = prefix;
    *rem_out = kk;
}

// ---------------------------------------------------------------------------
// Fused kernel: blocks 0..95 = per-(b,c) top-84; last-arriving block per b
// runs the GCN/structure/sort phase. Blocks >= 96 stream-copy hs rows 1..784.
// ---------------------------------------------------------------------------
__global__ void __launch_bounds__(256) fused_kernel(const float* __restrict__ x,
                                                    const float* __restrict__ w1,
                                                    const float4* __restrict__ hid4,
                                                    float4* __restrict__ out4,
                                                    int SEL, int copyA) {
    int blk = blockIdx.x;
    int tid = threadIdx.x;
    const int D4 = DD / 4;        // 192
    const int ND4 = NN * D4;      // 150720
    const int RPB = ND4 - D4;     // rows 1..784 float4s per batch

    if (blk >= NTOPK) {
        // -------- bulk copy of rows 1..784 (independent work) --------
        int q = (blk - NTOPK) * 1024 + tid;
        #pragma unroll
        for (int rep = 0; rep < 4; rep++) {
            int qq = q + rep * 256;
            if (qq < copyA) {
                int b = qq / RPB;
                int r = qq - b * RPB;
                int idx = b * ND4 + D4 + r;
                out4[idx] = hid4[idx];
            }
        }
        return;
    }

    int b = blk / CC;
    int c = blk - b * CC;

    __shared__ union {
        struct { unsigned ord[SS]; float sc[SS]; unsigned char selm[SS]; } t;
        struct { float pw[SS]; int cc[SS]; unsigned keys[SS]; } g;
    } U;
    __shared__ int      tk_w[8];
    __shared__ double   dredw[8];
    __shared__ float    fredw[8];
    __shared__ int      iredw[8];
    __shared__ float4   qredw[8];
    __shared__ float    s_mean, s_sv0, s_sv1, s_Pp, s_Pn;
    __shared__ int      s_anchor;
    __shared__ unsigned sel_list[64];
    __shared__ int      sel_cnt;
    __shared__ unsigned s_last;

    // ================= top-k phase =================
    const float* row = x + ((size_t)(b * CC + c) * NN) * NN + 1;  // x[b,c,0,1:]
    for (int s = tid; s < SS; s += 256) {
        float v = row[s];
        U.t.sc[s] = v;
        unsigned u = __float_as_uint(v);
        U.t.ord[s] = (u & 0x80000000u) ? ~u : (u | 0x80000000u);
    }
    __syncthreads();

    unsigned T; int rem;
    radix_select_desc(U.t.ord, SS, PATCH, &T, &rem);

    // tie scan: thread t owns s in [4t, 4t+4), 784 = 4*196
    int cnt = 0;
    if (tid < 196) {
        #pragma unroll
        for (int e = 0; e < 4; e++) cnt += (U.t.ord[4 * tid + e] == T);
    }
    int w = tid >> 5, l = tid & 31;
    int v = cnt;
    #pragma unroll
    for (int o = 1; o < 32; o <<= 1) {
        int up = __shfl_up_sync(0xffffffffu, v, o);
        if (l >= o) v += up;
    }
    if (l == 31) tk_w[w] = v;
    __syncthreads();
    int add = 0;
    #pragma unroll
    for (int ww = 0; ww < 8; ww++) add += (ww < w) ? tk_w[ww] : 0;
    int base = v - cnt + add;

    if (tid < 196) {
        int run = base;
        #pragma unroll
        for (int e = 0; e < 4; e++) {
            int s = 4 * tid + e;
            unsigned o = U.t.ord[s];
            bool sel;
            if (o > T) sel = true;
            else if (o == T) { sel = (run < rem); run++; }
            else sel = false;
            U.t.selm[s] = sel ? 1 : 0;
        }
    }
    __syncthreads();

    float* ns = g_newscore + (b * CC + c) * SS;
    unsigned char* gs = g_sel + (b * CC + c) * SS;
    for (int s = tid; s < SS; s += 256) {
        unsigned char m = U.t.selm[s];
        ns[s] = m ? U.t.sc[s] : U.t.sc[s] * 0.7f;
        gs[s] = m;
    }

    // ================= arrival sync: last block of batch b continues =========
    __threadfence();
    __syncthreads();
    if (tid == 0) s_last = atomicAdd(&g_done[b], 1u) % CC;
    __syncthreads();
    if (s_last != CC - 1) return;
    __threadfence();

    // ================= gcn phase (single block per b) =================
    // pw[s] = mean_c new_score; counts; double sum for mean
    double dsum = 0.0;
    if (tid < 196) {
        float4 acc = make_float4(0.f, 0.f, 0.f, 0.f);
        int c0 = 0, c1 = 0, c2 = 0, c3 = 0;
        #pragma unroll
        for (int cx = 0; cx < CC; cx++) {
            float4 vv = *(const float4*)(g_newscore + (b * CC + cx) * SS + 4 * tid);
            acc.x += vv.x; acc.y += vv.y; acc.z += vv.z; acc.w += vv.w;
            uchar4 mm = *(const uchar4*)(g_sel + (b * CC + cx) * SS + 4 * tid);
            c0 += mm.x; c1 += mm.y; c2 += mm.z; c3 += mm.w;
        }
        float p0 = acc.x / 12.f, p1 = acc.y / 12.f, p2 = acc.z / 12.f, p3 = acc.w / 12.f;
        U.g.pw[4 * tid + 0] = p0; U.g.cc[4 * tid + 0] = c0;
        U.g.pw[4 * tid + 1] = p1; U.g.cc[4 * tid + 1] = c1;
        U.g.pw[4 * tid + 2] = p2; U.g.cc[4 * tid + 2] = c2;
        U.g.pw[4 * tid + 3] = p3; U.g.cc[4 * tid + 3] = c3;
        dsum = (double)p0 + (double)p1 + (double)p2 + (double)p3;
    }
    // warp+cross-warp double reduction
    #pragma unroll
    for (int o = 16; o > 0; o >>= 1) dsum += __shfl_down_sync(0xffffffffu, dsum, o);
    if (l == 0) dredw[w] = dsum;
    __syncthreads();
    if (tid == 0) {
        double t2 = 0.0;
        #pragma unroll
        for (int ww = 0; ww < 8; ww++) t2 += dredw[ww];
        s_mean = (float)(t2 / 784.0);
    }
    __syncthreads();
    float mean = s_mean;

    // anchor = argmax_s (pw>mean ? pw : 0), first occurrence
    float bestv = -3.0e38f;
    int besti = 1 << 30;
    for (int s = tid; s < SS; s += 256) {
        float vv = (U.g.pw[s] > mean) ? U.g.pw[s] : 0.0f;
        if (vv > bestv || (vv == bestv && s < besti)) { bestv = vv; besti = s; }
    }
    #pragma unroll
    for (int o = 16; o > 0; o >>= 1) {
        float ov = __shfl_down_sync(0xffffffffu, bestv, o);
        int   oi = __shfl_down_sync(0xffffffffu, besti, o);
        if (ov > bestv || (ov == bestv && oi < besti)) { bestv = ov; besti = oi; }
    }
    if (l == 0) { fredw[w] = bestv; iredw[w] = besti; }
    __syncthreads();
    if (tid == 0) {
        float bv = fredw[0]; int bi = iredw[0];
        #pragma unroll
        for (int ww = 1; ww < 8; ww++) {
            if (fredw[ww] > bv || (fredw[ww] == bv && iredw[ww] < bi)) {
                bv = fredw[ww]; bi = iredw[ww];
            }
        }
        s_anchor = bi;
        g_pwa[b] = U.g.pw[bi];
    }
    __syncthreads();
    int anchor = s_anchor;
    int ai = anchor / HH, aj = anchor % HH;

    // sv = sum_s pw*(dist,ang); Pp/Pn = sum pw^2 by sign
    float sv0 = 0.f, sv1 = 0.f, Pp = 0.f, Pn = 0.f;
    const float PI_F = 3.14159265358979323846f;
    for (int s = tid; s < SS; s += 256) {
        int i = s / HH, j = s - i * HH;
        float rx = (float)(i - ai) / 28.0f;
        float ry = (float)(j - aj) / 28.0f;
        float dist = sqrtf(rx * rx + ry * ry);
        float ang = (atan2f(ry, rx) / PI_F + 1.0f) / 2.0f;
        float p = U.g.pw[s];
        sv0 += p * dist;
        sv1 += p * ang;
        if (p > 0.f) Pp += p * p;
        else if (p < 0.f) Pn += p * p;
    }
    #pragma unroll
    for (int o = 16; o > 0; o >>= 1) {
        sv0 += __shfl_down_sync(0xffffffffu, sv0, o);
        sv1 += __shfl_down_sync(0xffffffffu, sv1, o);
        Pp  += __shfl_down_sync(0xffffffffu, Pp, o);
        Pn  += __shfl_down_sync(0xffffffffu, Pn, o);
    }
    if (l == 0) qredw[w] = make_float4(sv0, sv1, Pp, Pn);
    __syncthreads();
    if (tid == 0) {
        float4 t4 = qredw[0];
        #pragma unroll
        for (int ww = 1; ww < 8; ww++) {
            t4.x += qredw[ww].x; t4.y += qredw[ww].y;
            t4.z += qredw[ww].z; t4.w += qredw[ww].w;
        }
        s_sv0 = t4.x; s_sv1 = t4.y; s_Pp = t4.z; s_Pn = t4.w;
    }
    __syncthreads();
    float vsv0 = s_sv0, vsv1 = s_sv1, vPp = s_Pp, vPn = s_Pn;

    // u[j] = v1[j]*(v1>0 ? Pp : Pn), v1 = sv @ w1
    for (int j = tid; j < 512; j += 256) {
        float v1 = vsv0 * w1[j] + vsv1 * w1[512 + j];
        g_u[b * 512 + j] = v1 * (v1 > 0.f ? vPp : vPn);
    }

    // 3x3 [1,2,1;2,4,2;1,2,1] conv on counts -> keys with count in top byte
    for (int s = tid; s < SS; s += 256) {
        int i = s / HH, j = s - i * HH;
        int acc = 0;
        #pragma unroll
        for (int di = -1; di <= 1; di++) {
            int ii = i + di;
            if (ii < 0 || ii >= HH) continue;
            #pragma unroll
            for (int dj = -1; dj <= 1; dj++) {
                int jj = j + dj;
                if (jj < 0 || jj >= HH) continue;
                int wgt = (2 - (di < 0 ? -di : di)) * (2 - (dj < 0 ? -dj : dj));
                acc += wgt * U.g.cc[ii * HH + jj];
            }
        }
        U.g.keys[s] = ((unsigned)acc << 24) | ((unsigned)(1023 - s) << 14);
    }
    if (tid == 0) sel_cnt = 0;
    __syncthreads();

    unsigned KT; int krem;
    radix_select_desc(U.g.keys, SS, SEL, &KT, &krem);  // keys unique

    for (int s = tid; s < SS; s += 256) {
        if (U.g.keys[s] >= KT) {
            int p = atomicAdd(&sel_cnt, 1);
            sel_list[p] = U.g.keys[s];
        }
    }
    __syncthreads();
    if (tid < SEL) {
        unsigned mk = sel_list[tid];
        int r = 0;
        for (int m = 0; m < SEL; m++) r += (sel_list[m] > mk) ? 1 : 0;
        g_patchidx[b * 64 + r] = 1024 - (int)((mk >> 14) & 1023u);
    }
}

// ---------------------------------------------------------------------------
// Finish kernel: blocks 0..95 = w2 matvec + leakyrelu + row0 write
// (b = blk/12, 64-col chunk = blk%12, 4-way j split). Blocks >= 96 gather
// the selected rows.
// ---------------------------------------------------------------------------
#define MVB 96

__global__ void __launch_bounds__(256) finish_kernel(const float4* __restrict__ hid4,
                                                     float4* __restrict__ out4,
                                                     const float* __restrict__ w2,
                                                     int SEL, int gatherTot) {
    int blk = blockIdx.x;
    int tid = threadIdx.x;
    const int D4 = DD / 4;
    const int ND4 = NN * D4;
    const int HS4 = BB * ND4;

    if (blk < MVB) {
        __shared__ float su[512];
        __shared__ float red[4 * 64];
        int b = blk / 12, kc = blk - b * 12;
        su[tid] = g_u[b * 512 + tid];
        su[256 + tid] = g_u[b * 512 + 256 + tid];
        __syncthreads();
        int col = tid & 63;
        int half = tid >> 6;            // 0..3 -> j in [half*128, half*128+128)
        const float* w2c = w2 + kc * 64 + col;
        float a0 = 0.f, a1 = 0.f;
        int jb = half * 128;
        #pragma unroll 16
        for (int j0 = 0; j0 < 128; j0 += 2) {
            a0 += su[jb + j0]     * w2c[(jb + j0)     * DD];
            a1 += su[jb + j0 + 1] * w2c[(jb + j0 + 1) * DD];
        }
        red[half * 64 + col] = a0 + a1;
        __syncthreads();
        if (tid < 64) {
            float s = red[tid] + red[64 + tid] + red[128 + tid] + red[192 + tid];
            float o = g_pwa[b] * s;
            float res = (o > 0.f) ? o : 0.2f * o;
            size_t idx = (size_t)b * (NN * DD) + kc * 64 + tid;
            ((float*)out4)[idx] = ((const float*)hid4)[idx] + res;
        }
        return;
    }

    int q = (blk - MVB) * 512 + tid;
    int perb = SEL * D4;
    #pragma unroll
    for (int rep = 0; rep < 2; rep++) {
        int qq = q + rep * 256;
        if (qq < gatherTot) {
            int b = qq / perb;
            int r = qq - b * perb;
            int i = r / D4;
            int k4 = r - i * D4;
            int rowi = g_patchidx[b * 64 + i];
            out4[HS4 + qq] = hid4[(b * NN + rowi) * D4 + k4];
        }
    }
}

// ---------------------------------------------------------------------------
extern "C" void kernel_launch(void* const* d_in, const int* in_sizes, int n_in,
                              void* d_out, int out_size) {
    const float* hidden = (const float*)d_in[0];
    const float* x      = (const float*)d_in[1];
    const float* w1     = (const float*)d_in[2];
    const float* w2     = (const float*)d_in[3];
    int SEL = (out_size - BB * NN * DD) / (BB * DD);

    const int D4 = DD / 4, ND4 = NN * D4;
    int copyA = BB * (ND4 - D4);               // rows 1..784 float4s
    int NC    = (copyA + 1023) / 1024;         // 4 float4 per thread
    fused_kernel<<<NTOPK + NC, 256>>>(x, w1, (const float4*)hidden,
                                      (float4*)d_out, SEL, copyA);

    int gatherTot = BB * SEL * D4;
    int NG = (gatherTot + 511) / 512;
    finish_kernel<<<MVB + NG, 256>>>((const float4*)hidden, (float4*)d_out,
                                     w2, SEL, gatherTot);
}